// round 1
// baseline (speedup 1.0000x reference)
#include <cuda_runtime.h>
#include <math.h>
#include <stdint.h>

#define BB 8
#define SS 4096
#define HH 2048
#define EE 8
#define CAP 512
#define NTOK (BB*SS)            /* 32768 */

#define K1_BLOCKS 256
#define K1_THREADS 128
#define TOK_PER_BLOCK 128

#define D_OFF ((size_t)0)
#define C_OFF ((size_t)NTOK*EE)          /* 262144 */
#define P_OFF ((size_t)2*NTOK*EE)        /* 524288 */
#define AUX_OFF ((size_t)3*NTOK*EE)      /* 786432 */
#define Z_OFF (AUX_OFF+1)

__device__ float g_wt[NTOK];
__device__ int   g_idx[NTOK];
__device__ float g_p2[K1_BLOCKS];
__device__ float g_z2[K1_BLOCKS];

// ---------------------------------------------------------------------------
// Kernel 1: router GEMM + softmax + argmax + probs + per-block loss partials
// Warp layout: 8 token-groups x 4 lanes. Group g owns tokens tokBase..tokBase+3.
// Lane s (0..3) covers h-slices (h16 + s*4 .. +3) of every 16-h chunk.
// W chunk (512 h) staged in SMEM with 16B pad per 128B block -> conflict-free.
// ---------------------------------------------------------------------------
__global__ __launch_bounds__(K1_THREADS) void router_kernel(
    const float* __restrict__ hs, const float* __restrict__ Wr,
    float* __restrict__ out)
{
    __shared__ float sW[128 * 36];   // 512 h * 8 e, padded (36 floats per 4-h region)
    __shared__ float sRedP[4];
    __shared__ float sRedZ[4];

    const int tid  = threadIdx.x;
    const int w    = tid >> 5;
    const int lane = tid & 31;
    const int g    = lane >> 2;
    const int s    = lane & 3;
    const int tokBase = blockIdx.x * TOK_PER_BLOCK + w * 32 + g * 4;

    float acc[4][8];
#pragma unroll
    for (int i = 0; i < 4; i++)
#pragma unroll
        for (int e = 0; e < 8; e++) acc[i][e] = 0.0f;

    const float4* __restrict__ hs4 = reinterpret_cast<const float4*>(hs);
    const float4* __restrict__ W4  = reinterpret_cast<const float4*>(Wr);

    for (int hc = 0; hc < HH; hc += 512) {
        __syncthreads();
        // stage W[hc..hc+512) into padded smem: 1024 float4 loads
#pragma unroll
        for (int q = tid; q < 1024; q += K1_THREADS) {
            int hl = q >> 1, part = q & 1;
            float4 v = W4[(hc + hl) * 2 + part];
            *reinterpret_cast<float4*>(&sW[(hl >> 2) * 36 + (hl & 3) * 8 + part * 4]) = v;
        }
        __syncthreads();

#pragma unroll 2
        for (int h16 = 0; h16 < 512; h16 += 16) {
            // lane's 4 h-rows of W: region r = h16/4 + s, 32 floats
            const float4* wp = reinterpret_cast<const float4*>(&sW[(h16 / 4 + s) * 36]);
            float4 wv[8];
#pragma unroll
            for (int j = 0; j < 8; j++) wv[j] = wp[j];

            const int hg = hc + h16 + s * 4;
#pragma unroll
            for (int i = 0; i < 4; i++) {
                float4 hv = hs4[((size_t)(tokBase + i) * HH + hg) >> 2];
                const float* hvp = &hv.x;
#pragma unroll
                for (int k = 0; k < 4; k++) {
                    float x = hvp[k];
                    float4 wa = wv[2 * k];
                    float4 wb = wv[2 * k + 1];
                    acc[i][0] += x * wa.x; acc[i][1] += x * wa.y;
                    acc[i][2] += x * wa.z; acc[i][3] += x * wa.w;
                    acc[i][4] += x * wb.x; acc[i][5] += x * wb.y;
                    acc[i][6] += x * wb.z; acc[i][7] += x * wb.w;
                }
            }
        }
    }

    // reduce K-partials across the 4 lanes of each token-group (bits 0,1)
#pragma unroll
    for (int i = 0; i < 4; i++)
#pragma unroll
        for (int e = 0; e < 8; e++) {
            float v = acc[i][e];
            v += __shfl_xor_sync(0xffffffffu, v, 1);
            v += __shfl_xor_sync(0xffffffffu, v, 2);
            acc[i][e] = v;
        }

    // lane s finalizes token tokBase + s  (select without dynamic indexing)
    const int tok = tokBase + s;
    float l[8];
#pragma unroll
    for (int e = 0; e < 8; e++) {
        float v = acc[0][e];
        if (s == 1) v = acc[1][e];
        if (s == 2) v = acc[2][e];
        if (s == 3) v = acc[3][e];
        l[e] = v;
    }

    // first-max argmax (matches jnp.argmax tie-breaking)
    float m = l[0]; int bi = 0;
#pragma unroll
    for (int e = 1; e < 8; e++) { if (l[e] > m) { m = l[e]; bi = e; } }

    float pe[8], sum = 0.0f;
#pragma unroll
    for (int e = 0; e < 8; e++) { pe[e] = expf(l[e] - m); sum += pe[e]; }
    float inv = 1.0f / sum;
    float p2 = 0.0f;
    float wmax = 0.0f;
#pragma unroll
    for (int e = 0; e < 8; e++) { pe[e] *= inv; p2 += pe[e] * pe[e]; if (e == bi) wmax = pe[e]; }
    float lse = m + logf(sum);
    float z2 = lse * lse;

    // write probs (2x float4, coalesced across the token-group)
    float4* po = reinterpret_cast<float4*>(out + P_OFF + (size_t)tok * 8);
    po[0] = make_float4(pe[0], pe[1], pe[2], pe[3]);
    po[1] = make_float4(pe[4], pe[5], pe[6], pe[7]);
    g_idx[tok] = bi;
    g_wt[tok]  = wmax;

    // deterministic block reduction of loss partials
#pragma unroll
    for (int off = 16; off > 0; off >>= 1) {
        p2 += __shfl_down_sync(0xffffffffu, p2, off);
        z2 += __shfl_down_sync(0xffffffffu, z2, off);
    }
    if (lane == 0) { sRedP[w] = p2; sRedZ[w] = z2; }
    __syncthreads();
    if (tid == 0) {
        float tp = 0.0f, tz = 0.0f;
#pragma unroll
        for (int i = 0; i < 4; i++) { tp += sRedP[i]; tz += sRedZ[i]; }
        g_p2[blockIdx.x] = tp;
        g_z2[blockIdx.x] = tz;
    }
}

// ---------------------------------------------------------------------------
// Kernel 2: per-batch-row capacity scan + dispatch/combine writes.
// One block per batch row. Thread t owns 8 consecutive tokens.
// Log-step inclusive scan of per-expert count vectors (padded stride 9).
// ---------------------------------------------------------------------------
__global__ __launch_bounds__(512) void dispatch_kernel(float* __restrict__ out)
{
    __shared__ int sc[512 * 9];
    const int b = blockIdx.x;
    const int t = threadIdx.x;
    const int base = b * SS + t * 8;

    int idx[8]; float wt[8];
    int cnt[8];
#pragma unroll
    for (int e = 0; e < 8; e++) cnt[e] = 0;
#pragma unroll
    for (int j = 0; j < 8; j++) {
        idx[j] = g_idx[base + j];
        wt[j]  = g_wt[base + j];
#pragma unroll
        for (int e = 0; e < 8; e++) cnt[e] += (idx[j] == e) ? 1 : 0;
    }
#pragma unroll
    for (int e = 0; e < 8; e++) sc[t * 9 + e] = cnt[e];
    __syncthreads();

    for (int off = 1; off < 512; off <<= 1) {
        int v[8];
        const bool act = (t >= off);
        if (act) {
#pragma unroll
            for (int e = 0; e < 8; e++) v[e] = sc[(t - off) * 9 + e];
        }
        __syncthreads();
        if (act) {
#pragma unroll
            for (int e = 0; e < 8; e++) sc[t * 9 + e] += v[e];
        }
        __syncthreads();
    }

    int run[8];   // exclusive prefix for this thread
#pragma unroll
    for (int e = 0; e < 8; e++) run[e] = sc[t * 9 + e] - cnt[e];

#pragma unroll
    for (int j = 0; j < 8; j++) {
        const int ej = idx[j];
        int pos = 0;
#pragma unroll
        for (int e = 0; e < 8; e++) pos += (ej == e) ? run[e] : 0;
        const bool keep = (pos < CAP);
#pragma unroll
        for (int e = 0; e < 8; e++) run[e] += (ej == e) ? 1 : 0;

        const float dv = keep ? 1.0f : 0.0f;
        float d[8];
#pragma unroll
        for (int e = 0; e < 8; e++) d[e] = (ej == e) ? dv : 0.0f;

        const size_t o = (size_t)(base + j) * 8;
        float4* dp = reinterpret_cast<float4*>(out + D_OFF + o);
        dp[0] = make_float4(d[0], d[1], d[2], d[3]);
        dp[1] = make_float4(d[4], d[5], d[6], d[7]);

        const float wj = wt[j];
        float4* cp = reinterpret_cast<float4*>(out + C_OFF + o);
        cp[0] = make_float4(d[0] * wj, d[1] * wj, d[2] * wj, d[3] * wj);
        cp[1] = make_float4(d[4] * wj, d[5] * wj, d[6] * wj, d[7] * wj);
    }
}

// ---------------------------------------------------------------------------
// Kernel 3: deterministic tree reduction of block partials -> aux_loss, z_loss
// ---------------------------------------------------------------------------
__global__ __launch_bounds__(256) void loss_kernel(float* __restrict__ out)
{
    __shared__ float sp[256];
    __shared__ float sz[256];
    const int t = threadIdx.x;
    sp[t] = g_p2[t];
    sz[t] = g_z2[t];
    __syncthreads();
#pragma unroll
    for (int off = 128; off > 0; off >>= 1) {
        if (t < off) { sp[t] += sp[t + off]; sz[t] += sz[t + off]; }
        __syncthreads();
    }
    if (t == 0) {
        out[AUX_OFF] = (sp[0] / (float)NTOK) * (float)EE;
        out[Z_OFF]   = sz[0] / (float)NTOK;
    }
}

// ---------------------------------------------------------------------------
extern "C" void kernel_launch(void* const* d_in, const int* in_sizes, int n_in,
                              void* d_out, int out_size)
{
    const float* hs = (const float*)d_in[0];
    const float* Wr = (const float*)d_in[1];
    // defensive: if the harness ordered inputs the other way, swap
    if (n_in >= 2 && in_sizes[0] == HH * EE && in_sizes[1] == NTOK * HH) {
        hs = (const float*)d_in[1];
        Wr = (const float*)d_in[0];
    }
    float* out = (float*)d_out;

    router_kernel<<<K1_BLOCKS, K1_THREADS>>>(hs, Wr, out);
    dispatch_kernel<<<BB, 512>>>(out);
    loss_kernel<<<1, 256>>>(out);
}

// round 3
// speedup vs baseline: 1.3907x; 1.3907x over previous
#include <cuda_runtime.h>
#include <math.h>
#include <stdint.h>

#define BB 8
#define SS 4096
#define HH 2048
#define EE 8
#define CAP 512
#define NTOK (BB*SS)            /* 32768 */

#define GSPLIT 4
#define KCHUNK 512              /* HH / GSPLIT */

#define K1_BLOCKS 256
#define K1_THREADS 128
#define TOK_PER_BLOCK 128

#define FIN_BLOCKS 128
#define FIN_THREADS 256

#define D_OFF ((size_t)0)
#define C_OFF ((size_t)NTOK*EE)          /* 262144 */
#define P_OFF ((size_t)2*NTOK*EE)        /* 524288 */
#define AUX_OFF ((size_t)3*NTOK*EE)      /* 786432 */
#define Z_OFF (AUX_OFF+1)

__device__ float g_part[(size_t)GSPLIT * NTOK * 8];   // partial logits per K-chunk
__device__ float g_wt[NTOK];
__device__ int   g_idx[NTOK];
__device__ float g_p2[FIN_BLOCKS];
__device__ float g_z2[FIN_BLOCKS];

// ---------------------------------------------------------------------------
// Kernel 1: partial router GEMM over one 512-wide K chunk (blockIdx.y).
// Warp: 8 token-groups x 4 lanes; lane s covers h-slices (h16+s*4..+3).
// W chunk staged in padded SMEM; W cached in regs, amortized over 4 tokens.
// ---------------------------------------------------------------------------
__global__ __launch_bounds__(K1_THREADS) void router_partial_kernel(
    const float* __restrict__ hs, const float* __restrict__ Wr)
{
    __shared__ float sW[128 * 36];   // 512 h-rows * 8 e, padded

    const int tid  = threadIdx.x;
    const int w    = tid >> 5;
    const int lane = tid & 31;
    const int g    = lane >> 2;
    const int s    = lane & 3;
    const int tokBase = blockIdx.x * TOK_PER_BLOCK + w * 32 + g * 4;
    const int hc = blockIdx.y * KCHUNK;

    float acc[4][8];
#pragma unroll
    for (int i = 0; i < 4; i++)
#pragma unroll
        for (int e = 0; e < 8; e++) acc[i][e] = 0.0f;

    const float4* __restrict__ hs4 = reinterpret_cast<const float4*>(hs);
    const float4* __restrict__ W4  = reinterpret_cast<const float4*>(Wr);

    // stage W[hc..hc+512) into padded smem: 1024 float4 loads
#pragma unroll
    for (int q = tid; q < 1024; q += K1_THREADS) {
        int hl = q >> 1, part = q & 1;
        float4 v = W4[(hc + hl) * 2 + part];
        *reinterpret_cast<float4*>(&sW[(hl >> 2) * 36 + (hl & 3) * 8 + part * 4]) = v;
    }
    __syncthreads();

#pragma unroll 2
    for (int h16 = 0; h16 < KCHUNK; h16 += 16) {
        const float4* wp = reinterpret_cast<const float4*>(&sW[(h16 / 4 + s) * 36]);
        float4 wv[8];
#pragma unroll
        for (int j = 0; j < 8; j++) wv[j] = wp[j];

        const int hg = hc + h16 + s * 4;
#pragma unroll
        for (int i = 0; i < 4; i++) {
            float4 hv = hs4[((size_t)(tokBase + i) * HH + hg) >> 2];
            const float* hvp = &hv.x;
#pragma unroll
            for (int k = 0; k < 4; k++) {
                float x = hvp[k];
                float4 wa = wv[2 * k];
                float4 wb = wv[2 * k + 1];
                acc[i][0] += x * wa.x; acc[i][1] += x * wa.y;
                acc[i][2] += x * wa.z; acc[i][3] += x * wa.w;
                acc[i][4] += x * wb.x; acc[i][5] += x * wb.y;
                acc[i][6] += x * wb.z; acc[i][7] += x * wb.w;
            }
        }
    }

    // reduce K-partials across the 4 lanes of each token-group
#pragma unroll
    for (int i = 0; i < 4; i++)
#pragma unroll
        for (int e = 0; e < 8; e++) {
            float v = acc[i][e];
            v += __shfl_xor_sync(0xffffffffu, v, 1);
            v += __shfl_xor_sync(0xffffffffu, v, 2);
            acc[i][e] = v;
        }

    // lane s writes token tokBase+s's 8 partials for this chunk
    const int tok = tokBase + s;
    float l[8];
#pragma unroll
    for (int e = 0; e < 8; e++) {
        float v = acc[0][e];
        if (s == 1) v = acc[1][e];
        if (s == 2) v = acc[2][e];
        if (s == 3) v = acc[3][e];
        l[e] = v;
    }
    float4* po = reinterpret_cast<float4*>(&g_part[((size_t)blockIdx.y * NTOK + tok) * 8]);
    po[0] = make_float4(l[0], l[1], l[2], l[3]);
    po[1] = make_float4(l[4], l[5], l[6], l[7]);
}

// ---------------------------------------------------------------------------
// Kernel 2: finalize — sum partials, softmax, argmax, probs, loss partials
// ---------------------------------------------------------------------------
__global__ __launch_bounds__(FIN_THREADS) void finalize_kernel(float* __restrict__ out)
{
    __shared__ float sRedP[8];
    __shared__ float sRedZ[8];
    const int tid = threadIdx.x;
    const int tok = blockIdx.x * FIN_THREADS + tid;

    const float4* p4 = reinterpret_cast<const float4*>(g_part);
    float4 a = p4[(size_t)tok * 2];
    float4 b = p4[(size_t)tok * 2 + 1];
#pragma unroll
    for (int y = 1; y < GSPLIT; y++) {
        float4 pa = p4[((size_t)y * NTOK + tok) * 2];
        float4 pb = p4[((size_t)y * NTOK + tok) * 2 + 1];
        a.x += pa.x; a.y += pa.y; a.z += pa.z; a.w += pa.w;
        b.x += pb.x; b.y += pb.y; b.z += pb.z; b.w += pb.w;
    }
    float l[8] = {a.x, a.y, a.z, a.w, b.x, b.y, b.z, b.w};

    // first-max argmax (matches jnp.argmax tie-breaking)
    float m = l[0]; int bi = 0;
#pragma unroll
    for (int e = 1; e < 8; e++) { if (l[e] > m) { m = l[e]; bi = e; } }

    float pe[8], sum = 0.0f;
#pragma unroll
    for (int e = 0; e < 8; e++) { pe[e] = expf(l[e] - m); sum += pe[e]; }
    float inv = 1.0f / sum;
    float p2 = 0.0f, wmax = 0.0f;
#pragma unroll
    for (int e = 0; e < 8; e++) { pe[e] *= inv; p2 += pe[e] * pe[e]; if (e == bi) wmax = pe[e]; }
    float lse = m + logf(sum);
    float z2 = lse * lse;

    float4* po = reinterpret_cast<float4*>(out + P_OFF + (size_t)tok * 8);
    po[0] = make_float4(pe[0], pe[1], pe[2], pe[3]);
    po[1] = make_float4(pe[4], pe[5], pe[6], pe[7]);
    g_idx[tok] = bi;
    g_wt[tok]  = wmax;

    // deterministic block reduction of loss partials
    const int w = tid >> 5, lane = tid & 31;
#pragma unroll
    for (int off = 16; off > 0; off >>= 1) {
        p2 += __shfl_down_sync(0xffffffffu, p2, off);
        z2 += __shfl_down_sync(0xffffffffu, z2, off);
    }
    if (lane == 0) { sRedP[w] = p2; sRedZ[w] = z2; }
    __syncthreads();
    if (tid == 0) {
        float tp = 0.0f, tz = 0.0f;
#pragma unroll
        for (int i = 0; i < 8; i++) { tp += sRedP[i]; tz += sRedZ[i]; }
        g_p2[blockIdx.x] = tp;
        g_z2[blockIdx.x] = tz;
    }
}

// ---------------------------------------------------------------------------
// Kernel 3: per-batch-row capacity scan + dispatch/combine writes.
// One block per batch row, 512 threads x 8 tokens. Counts packed as 8x16-bit
// fields in two uint64s -> warp-shuffle scan + one cross-warp combine.
// ---------------------------------------------------------------------------
__global__ __launch_bounds__(512) void dispatch_kernel(float* __restrict__ out)
{
    __shared__ unsigned long long sW0[16], sW1[16];
    const int b = blockIdx.x;
    const int t = threadIdx.x;
    const int w = t >> 5, lane = t & 31;
    const int base = b * SS + t * 8;

    int idx[8]; float wt[8];
    unsigned long long c0 = 0ull, c1 = 0ull;   // experts 0-3 | 4-7, 16-bit fields
#pragma unroll
    for (int j = 0; j < 8; j++) {
        idx[j] = g_idx[base + j];
        wt[j]  = g_wt[base + j];
        int sh = (idx[j] & 3) * 16;
        if (idx[j] < 4) c0 += (1ull << sh); else c1 += (1ull << sh);
    }
    unsigned long long i0 = c0, i1 = c1;       // inclusive scan within warp
#pragma unroll
    for (int off = 1; off < 32; off <<= 1) {
        unsigned long long v0 = __shfl_up_sync(0xffffffffu, i0, off);
        unsigned long long v1 = __shfl_up_sync(0xffffffffu, i1, off);
        if (lane >= off) { i0 += v0; i1 += v1; }
    }
    if (lane == 31) { sW0[w] = i0; sW1[w] = i1; }
    __syncthreads();
    unsigned long long wp0 = 0ull, wp1 = 0ull; // exclusive prefix of warp totals
    if (w > 0) {
#pragma unroll
        for (int i = 0; i < 15; i++) {
            if (i < w) { wp0 += sW0[i]; wp1 += sW1[i]; }
        }
    }
    unsigned long long r0 = wp0 + i0 - c0;     // exclusive per-thread prefix
    unsigned long long r1 = wp1 + i1 - c1;

#pragma unroll
    for (int j = 0; j < 8; j++) {
        const int ej = idx[j];
        const int sh = (ej & 3) * 16;
        unsigned long long word = (ej < 4) ? r0 : r1;
        const int pos = (int)((word >> sh) & 0xffffull);
        const bool keep = (pos < CAP);
        if (ej < 4) r0 += (1ull << sh); else r1 += (1ull << sh);

        const float dv = keep ? 1.0f : 0.0f;
        float d[8];
#pragma unroll
        for (int e = 0; e < 8; e++) d[e] = (ej == e) ? dv : 0.0f;

        const size_t o = (size_t)(base + j) * 8;
        float4* dp = reinterpret_cast<float4*>(out + D_OFF + o);
        dp[0] = make_float4(d[0], d[1], d[2], d[3]);
        dp[1] = make_float4(d[4], d[5], d[6], d[7]);

        const float wj = wt[j];
        float4* cp = reinterpret_cast<float4*>(out + C_OFF + o);
        cp[0] = make_float4(d[0] * wj, d[1] * wj, d[2] * wj, d[3] * wj);
        cp[1] = make_float4(d[4] * wj, d[5] * wj, d[6] * wj, d[7] * wj);
    }
}

// ---------------------------------------------------------------------------
// Kernel 4: deterministic tree reduction of block partials -> aux_loss, z_loss
// ---------------------------------------------------------------------------
__global__ __launch_bounds__(FIN_BLOCKS) void loss_kernel(float* __restrict__ out)
{
    __shared__ float sp[FIN_BLOCKS];
    __shared__ float sz[FIN_BLOCKS];
    const int t = threadIdx.x;
    sp[t] = g_p2[t];
    sz[t] = g_z2[t];
    __syncthreads();
#pragma unroll
    for (int off = FIN_BLOCKS / 2; off > 0; off >>= 1) {
        if (t < off) { sp[t] += sp[t + off]; sz[t] += sz[t + off]; }
        __syncthreads();
    }
    if (t == 0) {
        out[AUX_OFF] = (sp[0] / (float)NTOK) * (float)EE;
        out[Z_OFF]   = sz[0] / (float)NTOK;
    }
}

// ---------------------------------------------------------------------------
extern "C" void kernel_launch(void* const* d_in, const int* in_sizes, int n_in,
                              void* d_out, int out_size)
{
    const float* hs = (const float*)d_in[0];
    const float* Wr = (const float*)d_in[1];
    if (n_in >= 2 && in_sizes[0] == HH * EE && in_sizes[1] == NTOK * HH) {
        hs = (const float*)d_in[1];
        Wr = (const float*)d_in[0];
    }
    float* out = (float*)d_out;

    router_partial_kernel<<<dim3(K1_BLOCKS, GSPLIT), K1_THREADS>>>(hs, Wr);
    finalize_kernel<<<FIN_BLOCKS, FIN_THREADS>>>(out);
    dispatch_kernel<<<BB, 512>>>(out);
    loss_kernel<<<1, FIN_BLOCKS>>>(out);
}

// round 5
// speedup vs baseline: 1.5185x; 1.0919x over previous
#include <cuda_runtime.h>
#include <math.h>
#include <stdint.h>

#define BB 8
#define SS 4096
#define HH 2048
#define EE 8
#define CAP 512
#define NTOK (BB*SS)            /* 32768 */

#define GSPLIT 8
#define KCHUNK 256              /* HH / GSPLIT */

#define K1_BLOCKS 256
#define K1_THREADS 128
#define TOK_PER_BLOCK 128

#define FIN_BLOCKS 64           /* 512 tokens each == one capacity segment */
#define FIN_THREADS 512

#define D_OFF ((size_t)0)
#define C_OFF ((size_t)NTOK*EE)
#define P_OFF ((size_t)2*NTOK*EE)
#define AUX_OFF ((size_t)3*NTOK*EE)
#define Z_OFF (AUX_OFF+1)

__device__ float g_part[(size_t)GSPLIT * NTOK * 8];   // partial logits per K-chunk
__device__ float g_wt[NTOK];
__device__ int   g_idx[NTOK];
__device__ int   g_segcnt[FIN_BLOCKS * 8];            // per-segment expert counts
__device__ float g_p2[FIN_BLOCKS];
__device__ float g_z2[FIN_BLOCKS];

// ---- packed f32x2 helpers (Blackwell FFMA2 path) ---------------------------
__device__ __forceinline__ unsigned long long pack2(float x) {
    unsigned long long r; int xi = __float_as_int(x);
    asm("mov.b64 %0, {%1, %1};" : "=l"(r) : "r"(xi));
    return r;
}
__device__ __forceinline__ unsigned long long fma2(unsigned long long a,
    unsigned long long b, unsigned long long c) {
    unsigned long long d;
    asm("fma.rn.f32x2 %0, %1, %2, %3;" : "=l"(d) : "l"(a), "l"(b), "l"(c));
    return d;
}
__device__ __forceinline__ unsigned long long add2(unsigned long long a,
    unsigned long long b) {
    unsigned long long d;
    asm("add.rn.f32x2 %0, %1, %2;" : "=l"(d) : "l"(a), "l"(b));
    return d;
}
__device__ __forceinline__ float2 unpack2(unsigned long long v) {
    int lo, hi;
    asm("mov.b64 {%0, %1}, %2;" : "=r"(lo), "=r"(hi) : "l"(v));
    return make_float2(__int_as_float(lo), __int_as_float(hi));
}

// ---------------------------------------------------------------------------
// Kernel 1: partial router GEMM over one 256-wide K chunk (blockIdx.y).
// Warp: 8 token-groups x 4 lanes; lane s covers h-slices (h16+s*4..+3).
// Accumulators are packed f32x2 expert-pairs -> FFMA2.
// ---------------------------------------------------------------------------
__global__ __launch_bounds__(K1_THREADS) void router_partial_kernel(
    const float* __restrict__ hs, const float* __restrict__ Wr)
{
    __shared__ float sW[(KCHUNK / 4) * 36];   // 64 regions * 36 floats (padded)

    const int tid  = threadIdx.x;
    const int w    = tid >> 5;
    const int lane = tid & 31;
    const int g    = lane >> 2;
    const int s    = lane & 3;
    const int tokBase = blockIdx.x * TOK_PER_BLOCK + w * 32 + g * 4;
    const int hc = blockIdx.y * KCHUNK;

    unsigned long long acc[4][4];   // [token][expert-pair], f32x2 packed
#pragma unroll
    for (int i = 0; i < 4; i++)
#pragma unroll
        for (int p = 0; p < 4; p++) acc[i][p] = 0ull;   // bits of (0.0f,0.0f)

    const float4* __restrict__ hs4 = reinterpret_cast<const float4*>(hs);
    const float4* __restrict__ W4  = reinterpret_cast<const float4*>(Wr);

    // stage W[hc..hc+256) into padded smem: 512 float4 loads
#pragma unroll
    for (int q = tid; q < KCHUNK * 2; q += K1_THREADS) {
        int hl = q >> 1, part = q & 1;
        float4 v = W4[(hc + hl) * 2 + part];
        *reinterpret_cast<float4*>(&sW[(hl >> 2) * 36 + (hl & 3) * 8 + part * 4]) = v;
    }
    __syncthreads();

#pragma unroll 2
    for (int h16 = 0; h16 < KCHUNK; h16 += 16) {
        // lane's 4 h-rows of W as 8 pairs-of-pairs (LDS.128)
        const ulonglong2* wp = reinterpret_cast<const ulonglong2*>(&sW[(h16 / 4 + s) * 36]);
        ulonglong2 wv[8];
#pragma unroll
        for (int j = 0; j < 8; j++) wv[j] = wp[j];

        const int hg = hc + h16 + s * 4;
#pragma unroll
        for (int i = 0; i < 4; i++) {
            float4 hv = hs4[((size_t)(tokBase + i) * HH + hg) >> 2];
            const float* hvp = &hv.x;
#pragma unroll
            for (int k = 0; k < 4; k++) {
                unsigned long long xx = pack2(hvp[k]);
                acc[i][0] = fma2(xx, wv[2 * k].x,     acc[i][0]);
                acc[i][1] = fma2(xx, wv[2 * k].y,     acc[i][1]);
                acc[i][2] = fma2(xx, wv[2 * k + 1].x, acc[i][2]);
                acc[i][3] = fma2(xx, wv[2 * k + 1].y, acc[i][3]);
            }
        }
    }

    // reduce K-partials across the 4 lanes of each token-group (f32x2 adds)
#pragma unroll
    for (int i = 0; i < 4; i++)
#pragma unroll
        for (int p = 0; p < 4; p++) {
            unsigned long long v = acc[i][p];
            v = add2(v, __shfl_xor_sync(0xffffffffu, v, 1));
            v = add2(v, __shfl_xor_sync(0xffffffffu, v, 2));
            acc[i][p] = v;
        }

    // lane s takes token tokBase+s (static selection), unpack, write 8 floats
    const int tok = tokBase + s;
    unsigned long long sel[4];
#pragma unroll
    for (int p = 0; p < 4; p++) {
        unsigned long long v = acc[0][p];
        if (s == 1) v = acc[1][p];
        if (s == 2) v = acc[2][p];
        if (s == 3) v = acc[3][p];
        sel[p] = v;
    }
    float2 e01 = unpack2(sel[0]), e23 = unpack2(sel[1]);
    float2 e45 = unpack2(sel[2]), e67 = unpack2(sel[3]);
    float4* po = reinterpret_cast<float4*>(&g_part[((size_t)blockIdx.y * NTOK + tok) * 8]);
    po[0] = make_float4(e01.x, e01.y, e23.x, e23.y);
    po[1] = make_float4(e45.x, e45.y, e67.x, e67.y);
}

// ---------------------------------------------------------------------------
// Kernel 2: finalize — sum partials, softmax, argmax, probs, segment expert
// counts, per-block loss partials. One block == one 512-token segment.
// ---------------------------------------------------------------------------
__global__ __launch_bounds__(FIN_THREADS) void finalize_kernel(float* __restrict__ out)
{
    __shared__ float sRedP[16];
    __shared__ float sRedZ[16];
    __shared__ int   sCnt[8];
    const int tid = threadIdx.x;
    const int tok = blockIdx.x * FIN_THREADS + tid;

    if (tid < 8) sCnt[tid] = 0;
    __syncthreads();

    const float4* p4 = reinterpret_cast<const float4*>(g_part);
    float4 a = p4[(size_t)tok * 2];
    float4 b = p4[(size_t)tok * 2 + 1];
#pragma unroll
    for (int y = 1; y < GSPLIT; y++) {
        float4 pa = p4[((size_t)y * NTOK + tok) * 2];
        float4 pb = p4[((size_t)y * NTOK + tok) * 2 + 1];
        a.x += pa.x; a.y += pa.y; a.z += pa.z; a.w += pa.w;
        b.x += pb.x; b.y += pb.y; b.z += pb.z; b.w += pb.w;
    }
    float l[8] = {a.x, a.y, a.z, a.w, b.x, b.y, b.z, b.w};

    float m = l[0]; int bi = 0;
#pragma unroll
    for (int e = 1; e < 8; e++) { if (l[e] > m) { m = l[e]; bi = e; } }

    float pe[8], sum = 0.0f;
#pragma unroll
    for (int e = 0; e < 8; e++) { pe[e] = expf(l[e] - m); sum += pe[e]; }
    float inv = 1.0f / sum;
    float p2 = 0.0f, wmax = 0.0f;
#pragma unroll
    for (int e = 0; e < 8; e++) { pe[e] *= inv; p2 += pe[e] * pe[e]; if (e == bi) wmax = pe[e]; }
    float lse = m + logf(sum);
    float z2 = lse * lse;

    float4* po = reinterpret_cast<float4*>(out + P_OFF + (size_t)tok * 8);
    po[0] = make_float4(pe[0], pe[1], pe[2], pe[3]);
    po[1] = make_float4(pe[4], pe[5], pe[6], pe[7]);
    g_idx[tok] = bi;
    g_wt[tok]  = wmax;
    atomicAdd(&sCnt[bi], 1);   // counts: order-independent -> deterministic

    const int w = tid >> 5, lane = tid & 31;
#pragma unroll
    for (int off = 16; off > 0; off >>= 1) {
        p2 += __shfl_down_sync(0xffffffffu, p2, off);
        z2 += __shfl_down_sync(0xffffffffu, z2, off);
    }
    if (lane == 0) { sRedP[w] = p2; sRedZ[w] = z2; }
    __syncthreads();
    if (tid == 0) {
        float tp = 0.0f, tz = 0.0f;
#pragma unroll
        for (int i = 0; i < 16; i++) { tp += sRedP[i]; tz += sRedZ[i]; }
        g_p2[blockIdx.x] = tp;
        g_z2[blockIdx.x] = tz;
    }
    if (tid < 8) g_segcnt[blockIdx.x * 8 + tid] = sCnt[tid];
}

// ---------------------------------------------------------------------------
// Kernel 3: dispatch/combine. One block per 512-token segment (64 blocks),
// 1 token/thread. Position = same-row prior-segment counts + in-segment
// exclusive prefix (packed 16-bit fields, warp shuffle scan).
// ---------------------------------------------------------------------------
__global__ __launch_bounds__(512) void dispatch_kernel(float* __restrict__ out)
{
    __shared__ unsigned long long sW0[16], sW1[16];
    __shared__ int sBase[8];
    const int blk = blockIdx.x;
    const int b = blk >> 3, seg = blk & 7;
    const int t = threadIdx.x;
    const int w = t >> 5, lane = t & 31;
    const int tok = blk * 512 + t;

    if (t < 8) {
        int sbase = 0;
#pragma unroll
        for (int q = 0; q < 7; q++)
            if (q < seg) sbase += g_segcnt[((b << 3) + q) * 8 + t];
        sBase[t] = sbase;
    }

    const int e = g_idx[tok];
    const float wt = g_wt[tok];
    const int sh = (e & 3) * 16;
    unsigned long long c0 = (e < 4)  ? (1ull << sh) : 0ull;
    unsigned long long c1 = (e >= 4) ? (1ull << sh) : 0ull;

    unsigned long long i0 = c0, i1 = c1;     // inclusive warp scan
#pragma unroll
    for (int off = 1; off < 32; off <<= 1) {
        unsigned long long v0 = __shfl_up_sync(0xffffffffu, i0, off);
        unsigned long long v1 = __shfl_up_sync(0xffffffffu, i1, off);
        if (lane >= off) { i0 += v0; i1 += v1; }
    }
    if (lane == 31) { sW0[w] = i0; sW1[w] = i1; }
    __syncthreads();
    unsigned long long wp0 = 0ull, wp1 = 0ull;
#pragma unroll
    for (int i = 0; i < 15; i++)
        if (i < w) { wp0 += sW0[i]; wp1 += sW1[i]; }
    unsigned long long r0 = wp0 + i0 - c0;   // exclusive per-token prefix
    unsigned long long r1 = wp1 + i1 - c1;

    const int pos = sBase[e] + (int)((((e < 4) ? r0 : r1) >> sh) & 0xffffull);
    const float dv = (pos < CAP) ? 1.0f : 0.0f;

    float d[8];
#pragma unroll
    for (int q = 0; q < 8; q++) d[q] = (e == q) ? dv : 0.0f;

    const size_t o = (size_t)tok * 8;
    float4* dp = reinterpret_cast<float4*>(out + D_OFF + o);
    dp[0] = make_float4(d[0], d[1], d[2], d[3]);
    dp[1] = make_float4(d[4], d[5], d[6], d[7]);
    float4* cp = reinterpret_cast<float4*>(out + C_OFF + o);
    cp[0] = make_float4(d[0] * wt, d[1] * wt, d[2] * wt, d[3] * wt);
    cp[1] = make_float4(d[4] * wt, d[5] * wt, d[6] * wt, d[7] * wt);
}

// ---------------------------------------------------------------------------
// Kernel 4: single-warp deterministic reduction -> aux_loss, z_loss
// ---------------------------------------------------------------------------
__global__ __launch_bounds__(32) void loss_kernel(float* __restrict__ out)
{
    const int t = threadIdx.x;
    float p2 = g_p2[t] + g_p2[t + 32];
    float z2 = g_z2[t] + g_z2[t + 32];
#pragma unroll
    for (int off = 16; off > 0; off >>= 1) {
        p2 += __shfl_down_sync(0xffffffffu, p2, off);
        z2 += __shfl_down_sync(0xffffffffu, z2, off);
    }
    if (t == 0) {
        out[AUX_OFF] = (p2 / (float)NTOK) * (float)EE;
        out[Z_OFF]   = z2 / (float)NTOK;
    }
}

// ---------------------------------------------------------------------------
extern "C" void kernel_launch(void* const* d_in, const int* in_sizes, int n_in,
                              void* d_out, int out_size)
{
    const float* hs = (const float*)d_in[0];
    const float* Wr = (const float*)d_in[1];
    if (n_in >= 2 && in_sizes[0] == HH * EE && in_sizes[1] == NTOK * HH) {
        hs = (const float*)d_in[1];
        Wr = (const float*)d_in[0];
    }
    float* out = (float*)d_out;

    router_partial_kernel<<<dim3(K1_BLOCKS, GSPLIT), K1_THREADS>>>(hs, Wr);
    finalize_kernel<<<FIN_BLOCKS, FIN_THREADS>>>(out);
    dispatch_kernel<<<FIN_BLOCKS, 512>>>(out);
    loss_kernel<<<1, 32>>>(out);
}

// round 8
// speedup vs baseline: 1.6164x; 1.0645x over previous
#include <cuda_runtime.h>
#include <math.h>
#include <stdint.h>

#define BB 8
#define SS 4096
#define HH 2048
#define EE 8
#define CAP 512
#define NTOK (BB*SS)            /* 32768 */

#define GSPLIT 8
#define KCHUNK 256              /* HH / GSPLIT */

#define K1_BLOCKS 256
#define K1_THREADS 128
#define TOK_PER_BLOCK 128

#define FIN_BLOCKS 64           /* 512 tokens each == one capacity segment */
#define FIN_THREADS 512

#define D_OFF ((size_t)0)
#define C_OFF ((size_t)NTOK*EE)
#define P_OFF ((size_t)2*NTOK*EE)
#define AUX_OFF ((size_t)3*NTOK*EE)
#define Z_OFF (AUX_OFF+1)

__device__ float g_part[(size_t)GSPLIT * NTOK * 8];   // partial logits per K-chunk
__device__ float g_wt[NTOK];
__device__ int   g_idx[NTOK];
__device__ int   g_segcnt[FIN_BLOCKS * 8];            // per-segment expert counts
__device__ float g_p2[FIN_BLOCKS];
__device__ float g_z2[FIN_BLOCKS];

// ---- packed f32x2 helpers (Blackwell FFMA2 path) ---------------------------
__device__ __forceinline__ unsigned long long pack2(float x) {
    unsigned long long r; int xi = __float_as_int(x);
    asm("mov.b64 %0, {%1, %1};" : "=l"(r) : "r"(xi));
    return r;
}
__device__ __forceinline__ unsigned long long fma2(unsigned long long a,
    unsigned long long b, unsigned long long c) {
    unsigned long long d;
    asm("fma.rn.f32x2 %0, %1, %2, %3;" : "=l"(d) : "l"(a), "l"(b), "l"(c));
    return d;
}
__device__ __forceinline__ unsigned long long add2(unsigned long long a,
    unsigned long long b) {
    unsigned long long d;
    asm("add.rn.f32x2 %0, %1, %2;" : "=l"(d) : "l"(a), "l"(b));
    return d;
}
__device__ __forceinline__ float2 unpack2(unsigned long long v) {
    int lo, hi;
    asm("mov.b64 {%0, %1}, %2;" : "=r"(lo), "=r"(hi) : "l"(v));
    return make_float2(__int_as_float(lo), __int_as_float(hi));
}

// ---------------------------------------------------------------------------
// Kernel 1: partial router GEMM over one 256-wide K chunk (blockIdx.y).
// Warp: 8 token-groups x 4 lanes; lane s covers h-slices (h16+s*4..+3).
// Accumulators are packed f32x2 expert-pairs -> FFMA2. unroll 4 -> 16 LDG.128
// batched per lane for high MLP against DRAM latency.
// ---------------------------------------------------------------------------
__global__ __launch_bounds__(K1_THREADS, 5) void router_partial_kernel(
    const float* __restrict__ hs, const float* __restrict__ Wr)
{
    __shared__ float sW[(KCHUNK / 4) * 36];   // 64 regions * 36 floats (padded)

    const int tid  = threadIdx.x;
    const int w    = tid >> 5;
    const int lane = tid & 31;
    const int g    = lane >> 2;
    const int s    = lane & 3;
    const int tokBase = blockIdx.x * TOK_PER_BLOCK + w * 32 + g * 4;
    const int hc = blockIdx.y * KCHUNK;

    unsigned long long acc[4][4];   // [token][expert-pair], f32x2 packed
#pragma unroll
    for (int i = 0; i < 4; i++)
#pragma unroll
        for (int p = 0; p < 4; p++) acc[i][p] = 0ull;

    const float4* __restrict__ hs4 = reinterpret_cast<const float4*>(hs);
    const float4* __restrict__ W4  = reinterpret_cast<const float4*>(Wr);

    // stage W[hc..hc+256) into padded smem: 512 float4 loads
#pragma unroll
    for (int q = tid; q < KCHUNK * 2; q += K1_THREADS) {
        int hl = q >> 1, part = q & 1;
        float4 v = W4[(hc + hl) * 2 + part];
        *reinterpret_cast<float4*>(&sW[(hl >> 2) * 36 + (hl & 3) * 8 + part * 4]) = v;
    }
    __syncthreads();

#pragma unroll 4
    for (int h16 = 0; h16 < KCHUNK; h16 += 16) {
        // lane's 4 h-rows of W as 8 pairs-of-pairs (LDS.128)
        const ulonglong2* wp = reinterpret_cast<const ulonglong2*>(&sW[(h16 / 4 + s) * 36]);
        ulonglong2 wv[8];
#pragma unroll
        for (int j = 0; j < 8; j++) wv[j] = wp[j];

        const int hg = hc + h16 + s * 4;
#pragma unroll
        for (int i = 0; i < 4; i++) {
            float4 hv = hs4[((size_t)(tokBase + i) * HH + hg) >> 2];
            const float* hvp = &hv.x;
#pragma unroll
            for (int k = 0; k < 4; k++) {
                unsigned long long xx = pack2(hvp[k]);
                acc[i][0] = fma2(xx, wv[2 * k].x,     acc[i][0]);
                acc[i][1] = fma2(xx, wv[2 * k].y,     acc[i][1]);
                acc[i][2] = fma2(xx, wv[2 * k + 1].x, acc[i][2]);
                acc[i][3] = fma2(xx, wv[2 * k + 1].y, acc[i][3]);
            }
        }
    }

    // reduce K-partials across the 4 lanes of each token-group (f32x2 adds)
#pragma unroll
    for (int i = 0; i < 4; i++)
#pragma unroll
        for (int p = 0; p < 4; p++) {
            unsigned long long v = acc[i][p];
            v = add2(v, __shfl_xor_sync(0xffffffffu, v, 1));
            v = add2(v, __shfl_xor_sync(0xffffffffu, v, 2));
            acc[i][p] = v;
        }

    // lane s takes token tokBase+s (static selection), unpack, write 8 floats
    const int tok = tokBase + s;
    unsigned long long sel[4];
#pragma unroll
    for (int p = 0; p < 4; p++) {
        unsigned long long v = acc[0][p];
        if (s == 1) v = acc[1][p];
        if (s == 2) v = acc[2][p];
        if (s == 3) v = acc[3][p];
        sel[p] = v;
    }
    float2 e01 = unpack2(sel[0]), e23 = unpack2(sel[1]);
    float2 e45 = unpack2(sel[2]), e67 = unpack2(sel[3]);
    float4* po = reinterpret_cast<float4*>(&g_part[((size_t)blockIdx.y * NTOK + tok) * 8]);
    po[0] = make_float4(e01.x, e01.y, e23.x, e23.y);
    po[1] = make_float4(e45.x, e45.y, e67.x, e67.y);
}

// ---------------------------------------------------------------------------
// Kernel 2: finalize — sum partials, softmax, argmax, probs, segment expert
// counts, per-block loss partials. One block == one 512-token segment.
// ---------------------------------------------------------------------------
__global__ __launch_bounds__(FIN_THREADS) void finalize_kernel(float* __restrict__ out)
{
    __shared__ float sRedP[16];
    __shared__ float sRedZ[16];
    __shared__ int   sCnt[8];
    const int tid = threadIdx.x;
    const int tok = blockIdx.x * FIN_THREADS + tid;

    if (tid < 8) sCnt[tid] = 0;
    __syncthreads();

    const float4* p4 = reinterpret_cast<const float4*>(g_part);
    float4 a = p4[(size_t)tok * 2];
    float4 b = p4[(size_t)tok * 2 + 1];
#pragma unroll
    for (int y = 1; y < GSPLIT; y++) {
        float4 pa = p4[((size_t)y * NTOK + tok) * 2];
        float4 pb = p4[((size_t)y * NTOK + tok) * 2 + 1];
        a.x += pa.x; a.y += pa.y; a.z += pa.z; a.w += pa.w;
        b.x += pb.x; b.y += pb.y; b.z += pb.z; b.w += pb.w;
    }
    float l[8] = {a.x, a.y, a.z, a.w, b.x, b.y, b.z, b.w};

    float m = l[0]; int bi = 0;
#pragma unroll
    for (int e = 1; e < 8; e++) { if (l[e] > m) { m = l[e]; bi = e; } }

    float pe[8], sum = 0.0f;
#pragma unroll
    for (int e = 0; e < 8; e++) { pe[e] = expf(l[e] - m); sum += pe[e]; }
    float inv = 1.0f / sum;
    float p2 = 0.0f, wmax = 0.0f;
#pragma unroll
    for (int e = 0; e < 8; e++) { pe[e] *= inv; p2 += pe[e] * pe[e]; if (e == bi) wmax = pe[e]; }
    float lse = m + logf(sum);
    float z2 = lse * lse;

    float4* po = reinterpret_cast<float4*>(out + P_OFF + (size_t)tok * 8);
    po[0] = make_float4(pe[0], pe[1], pe[2], pe[3]);
    po[1] = make_float4(pe[4], pe[5], pe[6], pe[7]);
    g_idx[tok] = bi;
    g_wt[tok]  = wmax;
    atomicAdd(&sCnt[bi], 1);   // counts: order-independent -> deterministic

    const int w = tid >> 5, lane = tid & 31;
#pragma unroll
    for (int off = 16; off > 0; off >>= 1) {
        p2 += __shfl_down_sync(0xffffffffu, p2, off);
        z2 += __shfl_down_sync(0xffffffffu, z2, off);
    }
    if (lane == 0) { sRedP[w] = p2; sRedZ[w] = z2; }
    __syncthreads();
    if (tid == 0) {
        float tp = 0.0f, tz = 0.0f;
#pragma unroll
        for (int i = 0; i < 16; i++) { tp += sRedP[i]; tz += sRedZ[i]; }
        g_p2[blockIdx.x] = tp;
        g_z2[blockIdx.x] = tz;
    }
    if (tid < 8) g_segcnt[blockIdx.x * 8 + tid] = sCnt[tid];
}

// ---------------------------------------------------------------------------
// Kernel 3: dispatch/combine + loss. One block per 512-token segment,
// 1 token/thread. Position = same-row prior-segment counts + in-segment
// exclusive prefix (packed 16-bit fields, warp shuffle scan).
// Block 0 warp 0 also reduces the 64 loss partials (kernel boundary after
// finalize is the grid barrier -> g_p2/g_z2 complete and visible).
// ---------------------------------------------------------------------------
__global__ __launch_bounds__(512) void dispatch_kernel(float* __restrict__ out)
{
    __shared__ unsigned long long sW0[16], sW1[16];
    __shared__ int sBase[8];
    const int blk = blockIdx.x;
    const int b = blk >> 3, seg = blk & 7;
    const int t = threadIdx.x;
    const int w = t >> 5, lane = t & 31;
    const int tok = blk * 512 + t;

    // loss reduction folded in (block 0, warp 0)
    if (blk == 0 && w == 0) {
        float lp = g_p2[lane] + g_p2[lane + 32];
        float lz = g_z2[lane] + g_z2[lane + 32];
#pragma unroll
        for (int off = 16; off > 0; off >>= 1) {
            lp += __shfl_down_sync(0xffffffffu, lp, off);
            lz += __shfl_down_sync(0xffffffffu, lz, off);
        }
        if (lane == 0) {
            out[AUX_OFF] = (lp / (float)NTOK) * (float)EE;
            out[Z_OFF]   = lz / (float)NTOK;
        }
    }

    if (t < 8) {
        int sbase = 0;
#pragma unroll
        for (int q = 0; q < 7; q++)
            if (q < seg) sbase += g_segcnt[((b << 3) + q) * 8 + t];
        sBase[t] = sbase;
    }

    const int e = g_idx[tok];
    const float wt = g_wt[tok];
    const int sh = (e & 3) * 16;
    unsigned long long c0 = (e < 4)  ? (1ull << sh) : 0ull;
    unsigned long long c1 = (e >= 4) ? (1ull << sh) : 0ull;

    unsigned long long i0 = c0, i1 = c1;     // inclusive warp scan
#pragma unroll
    for (int off = 1; off < 32; off <<= 1) {
        unsigned long long v0 = __shfl_up_sync(0xffffffffu, i0, off);
        unsigned long long v1 = __shfl_up_sync(0xffffffffu, i1, off);
        if (lane >= off) { i0 += v0; i1 += v1; }
    }
    if (lane == 31) { sW0[w] = i0; sW1[w] = i1; }
    __syncthreads();
    unsigned long long wp0 = 0ull, wp1 = 0ull;
#pragma unroll
    for (int i = 0; i < 15; i++)
        if (i < w) { wp0 += sW0[i]; wp1 += sW1[i]; }
    unsigned long long r0 = wp0 + i0 - c0;   // exclusive per-token prefix
    unsigned long long r1 = wp1 + i1 - c1;

    const int pos = sBase[e] + (int)((((e < 4) ? r0 : r1) >> sh) & 0xffffull);
    const float dv = (pos < CAP) ? 1.0f : 0.0f;

    float d[8];
#pragma unroll
    for (int q = 0; q < 8; q++) d[q] = (e == q) ? dv : 0.0f;

    const size_t o = (size_t)tok * 8;
    float4* dp = reinterpret_cast<float4*>(out + D_OFF + o);
    dp[0] = make_float4(d[0], d[1], d[2], d[3]);
    dp[1] = make_float4(d[4], d[5], d[6], d[7]);
    float4* cp = reinterpret_cast<float4*>(out + C_OFF + o);
    cp[0] = make_float4(d[0] * wt, d[1] * wt, d[2] * wt, d[3] * wt);
    cp[1] = make_float4(d[4] * wt, d[5] * wt, d[6] * wt, d[7] * wt);
}

// ---------------------------------------------------------------------------
extern "C" void kernel_launch(void* const* d_in, const int* in_sizes, int n_in,
                              void* d_out, int out_size)
{
    const float* hs = (const float*)d_in[0];
    const float* Wr = (const float*)d_in[1];
    if (n_in >= 2 && in_sizes[0] == HH * EE && in_sizes[1] == NTOK * HH) {
        hs = (const float*)d_in[1];
        Wr = (const float*)d_in[0];
    }
    float* out = (float*)d_out;

    router_partial_kernel<<<dim3(K1_BLOCKS, GSPLIT), K1_THREADS>>>(hs, Wr);
    finalize_kernel<<<FIN_BLOCKS, FIN_THREADS>>>(out);
    dispatch_kernel<<<FIN_BLOCKS, 512>>>(out);
}